// round 9
// baseline (speedup 1.0000x reference)
#include <cuda_runtime.h>
#include <cstdint>

#define N_NODES 100000
#define E_EDGES 1600000
#define F       128
#define C_OUT   64

// ---- device scratch ----
__device__ int   g_cnt[N_NODES];                 // in-degree histogram (excl. self)
__device__ int   g_ptr[N_NODES + 1];             // CSR row pointers (by target)
__device__ int   g_pos[N_NODES];                 // fill cursors
__device__ int   g_bsum[128];                    // per-block sums from scan1 (nbs<=128)
__device__ int   g_csr[E_EDGES];                 // source node per CSR slot
__device__ float g_dinv[N_NODES];
__device__ float g_wcomb[F * C_OUT];             // W_gcn @ W_fc^T
__device__ float g_xws[(size_t)N_NODES * C_OUT]; // dinv * (x @ Wcomb)
__device__ float g_bfc2[C_OUT];                  // b_fc + W_fc @ b_gcn

// ==================== fused setup: wcomb + bfc2 + zero cnt ====================
// blocks [0,1024): wcomb.  block 1024: bfc2.  blocks >1024: zero g_cnt.
__global__ void k_setup(const float* __restrict__ Wg, const float* __restrict__ Wfc,
                        const float* __restrict__ bgcn, const float* __restrict__ bfc,
                        int n) {
    int b = blockIdx.x;
    int t = threadIdx.x;
    int lane = t & 31;
    int w = t >> 5;
    if (b < 1024) {
        int idx = b * 8 + w;                  // 0..8191
        int k = idx >> 6, c = idx & 63;
        const float* wg = Wg + k * F;
        const float* wf = Wfc + c * F;
        float s = wg[lane] * wf[lane];
        s = fmaf(wg[lane + 32], wf[lane + 32], s);
        s = fmaf(wg[lane + 64], wf[lane + 64], s);
        s = fmaf(wg[lane + 96], wf[lane + 96], s);
#pragma unroll
        for (int o = 16; o > 0; o >>= 1) s += __shfl_xor_sync(0xffffffffu, s, o);
        if (lane == 0) g_wcomb[idx] = s;
        return;
    }
    if (b == 1024) {
#pragma unroll
        for (int cc = 0; cc < 8; ++cc) {
            int c = w * 8 + cc;
            const float* wf = Wfc + c * F;
            float s = bgcn[lane] * wf[lane];
            s = fmaf(bgcn[lane + 32], wf[lane + 32], s);
            s = fmaf(bgcn[lane + 64], wf[lane + 64], s);
            s = fmaf(bgcn[lane + 96], wf[lane + 96], s);
#pragma unroll
            for (int o = 16; o > 0; o >>= 1) s += __shfl_xor_sync(0xffffffffu, s, o);
            if (lane == 0) g_bfc2[c] = s + bfc[c];
        }
        return;
    }
    // zero g_cnt: 1024 ints per block
    int base = (b - 1025) * 1024 + t * 4;
    if (base + 3 < n) *(int4*)&g_cnt[base] = make_int4(0, 0, 0, 0);
    else for (int j = base; j < n; ++j) g_cnt[j] = 0;
}

// ==================== histogram over targets ====================
__global__ void k_hist(const int* __restrict__ col, int e) {
    int base = (blockIdx.x * blockDim.x + threadIdx.x) * 4;
    if (base >= e) return;
    if (base + 3 < e) {
        int4 c = *(const int4*)&col[base];
        atomicAdd(&g_cnt[c.x], 1);
        atomicAdd(&g_cnt[c.y], 1);
        atomicAdd(&g_cnt[c.z], 1);
        atomicAdd(&g_cnt[c.w], 1);
    } else {
        for (int j = base; j < e; ++j) atomicAdd(&g_cnt[col[j]], 1);
    }
}

// ==================== scan pass 1: per-block local scan + block sums ====================
__global__ void k_scan1(int n) {
    __shared__ int wsh[8];
    __shared__ int woff[8];
    int t = threadIdx.x, b = blockIdx.x;
    int base = b * 1024 + t * 4;
    int x0 = 0, x1 = 0, x2 = 0, x3 = 0;
    if (base + 3 < n) {
        int4 v = *(const int4*)&g_cnt[base];
        x0 = v.x; x1 = v.y; x2 = v.z; x3 = v.w;
    } else if (base < n) {
        x0 = g_cnt[base];
        if (base + 1 < n) x1 = g_cnt[base + 1];
        if (base + 2 < n) x2 = g_cnt[base + 2];
    }
    int s0 = x0, s1 = s0 + x1, s2 = s1 + x2, s3 = s2 + x3;
    int lane = t & 31, w = t >> 5;
    int ws = s3;
#pragma unroll
    for (int o = 1; o < 32; o <<= 1) {
        int u = __shfl_up_sync(0xffffffffu, ws, o);
        if (lane >= o) ws += u;
    }
    if (lane == 31) wsh[w] = ws;
    __syncthreads();
    if (t == 0) {
        int acc = 0;
#pragma unroll
        for (int i = 0; i < 8; ++i) { woff[i] = acc; acc += wsh[i]; }
        g_bsum[b] = acc;
    }
    __syncthreads();
    int excl = woff[w] + ws - s3;
    if (base < n)     g_ptr[base]     = excl;
    if (base + 1 < n) g_ptr[base + 1] = excl + s0;
    if (base + 2 < n) g_ptr[base + 2] = excl + s1;
    if (base + 3 < n) g_ptr[base + 3] = excl + s2;
}

// ==================== scan pass 2 (fused): add block offset; pos/dinv ====================
// each block recomputes its own offset = sum of g_bsum[0..b) — scan2 kernel eliminated
__global__ void k_scan3(int n, int e, int nbs) {
    __shared__ int s_off;
    int t = threadIdx.x, b = blockIdx.x;
    // offset = sum of g_bsum[i] for i < b   (nbs <= 128)
    int lane = t & 31;
    if (t < 128) {
        int v = (t < b && t < nbs) ? g_bsum[t] : 0;
#pragma unroll
        for (int o = 16; o > 0; o >>= 1) v += __shfl_xor_sync(0xffffffffu, v, o);
        __shared__ int psum[4];
        if (lane == 0) psum[t >> 5] = v;
        __syncthreads();
        if (t == 0) s_off = psum[0] + psum[1] + psum[2] + psum[3];
    }
    __syncthreads();
    int off = s_off;
    int base = b * 1024 + t * 4;
#pragma unroll
    for (int j = 0; j < 4; ++j) {
        int i = base + j;
        if (i < n) {
            int p = g_ptr[i] + off;
            g_ptr[i] = p;
            g_pos[i] = p;
            g_dinv[i] = rsqrtf((float)(g_cnt[i] + 1));
        }
    }
    if (b == 0 && t == 0) g_ptr[n] = e;
}

// ==================== CSR fill (4 edges/thread) ====================
__global__ void k_fill(const int* __restrict__ ei, int e) {
    int i = (blockIdx.x * blockDim.x + threadIdx.x) * 4;
    if (i >= e) return;
    if (i + 3 < e) {
        int4 rows = *(const int4*)&ei[i];       // e % 4 == 0 -> aligned
        int4 cols = *(const int4*)&ei[e + i];
        int p0 = atomicAdd(&g_pos[cols.x], 1); g_csr[p0] = rows.x;
        int p1 = atomicAdd(&g_pos[cols.y], 1); g_csr[p1] = rows.y;
        int p2 = atomicAdd(&g_pos[cols.z], 1); g_csr[p2] = rows.z;
        int p3 = atomicAdd(&g_pos[cols.w], 1); g_csr[p3] = rows.w;
    } else {
        for (int j = i; j < e; ++j) {
            int p = atomicAdd(&g_pos[ei[e + j]], 1);
            g_csr[p] = ei[j];
        }
    }
}

// ==================== GEMM: xws = dinv * (x @ Wcomb) ====================
__global__ void k_xw(const float* __restrict__ x, int n) {
    extern __shared__ float sh[];
    float* Wsm = sh;               // 128*64 = 32 KB  [k][c]
    float* Xsm = sh + F * C_OUT;   // 128*128 = 64 KB [r][k]

    int t = threadIdx.x;
    for (int i = t; i < (F * C_OUT) / 4; i += 256)
        ((float4*)Wsm)[i] = ((const float4*)g_wcomb)[i];

    int base = blockIdx.x * 128;
    for (int i = t; i < 128 * 32; i += 256) {
        int rr = i >> 5, cc = i & 31;
        int r = base + rr;
        float4 v = make_float4(0.f, 0.f, 0.f, 0.f);
        if (r < n) v = ((const float4*)x)[(size_t)r * 32 + cc];
        ((float4*)Xsm)[i] = v;
    }
    __syncthreads();

    int tx = t & 15;
    int ty = t >> 4;
    int c0 = tx * 4, r0 = ty * 8;

    float acc[8][4];
#pragma unroll
    for (int i = 0; i < 8; ++i)
#pragma unroll
        for (int j = 0; j < 4; ++j) acc[i][j] = 0.f;

#pragma unroll 4
    for (int k = 0; k < F; ++k) {
        float4 w = *(const float4*)&Wsm[k * C_OUT + c0];
#pragma unroll
        for (int i = 0; i < 8; ++i) {
            float xv = Xsm[(r0 + i) * F + k];
            acc[i][0] = fmaf(xv, w.x, acc[i][0]);
            acc[i][1] = fmaf(xv, w.y, acc[i][1]);
            acc[i][2] = fmaf(xv, w.z, acc[i][2]);
            acc[i][3] = fmaf(xv, w.w, acc[i][3]);
        }
    }

#pragma unroll
    for (int i = 0; i < 8; ++i) {
        int r = base + r0 + i;
        if (r < n) {
            float dv = g_dinv[r];
            float4 v;
            v.x = dv * acc[i][0];
            v.y = dv * acc[i][1];
            v.z = dv * acc[i][2];
            v.w = dv * acc[i][3];
            *(float4*)&g_xws[(size_t)r * C_OUT + c0] = v;
        }
    }
}

// ==================== gather: out = dinv_r*(xws[r] + sum xws[nbr]) + bfc2 ====================
// 16 threads per node; CSR chunk of 16 loaded coalesced, broadcast via half-warp shfl
__global__ void k_gather(float* __restrict__ out, int n) {
    int gt = blockIdx.x * blockDim.x + threadIdx.x;
    int r = gt >> 4;
    if (r >= n) return;
    int lane16 = threadIdx.x & 15;
    unsigned mask = 0xFFFFu << (threadIdx.x & 16);   // my half-warp
    int l4 = lane16 * 4;

    int p0 = __ldg(&g_ptr[r]);
    int p1 = __ldg(&g_ptr[r + 1]);

    float4 acc = *(const float4*)&g_xws[(size_t)r * C_OUT + l4];  // self-loop

    for (int chunk = p0; chunk < p1; chunk += 16) {
        int j = chunk + lane16;
        int myidx = (j < p1) ? __ldg(&g_csr[j]) : 0;   // coalesced 16-wide
        int cnt = min(16, p1 - chunk);
#pragma unroll 4
        for (int k = 0; k < cnt; ++k) {
            int idx = __shfl_sync(mask, myidx, k, 16);
            float4 v = *(const float4*)&g_xws[(size_t)idx * C_OUT + l4];
            acc.x += v.x; acc.y += v.y; acc.z += v.z; acc.w += v.w;
        }
    }

    float dvr = __ldg(&g_dinv[r]);
    float4 b = *(const float4*)&g_bfc2[l4];
    float4 o;
    o.x = fmaf(dvr, acc.x, b.x);
    o.y = fmaf(dvr, acc.y, b.y);
    o.z = fmaf(dvr, acc.z, b.z);
    o.w = fmaf(dvr, acc.w, b.w);
    *(float4*)&out[(size_t)r * C_OUT + l4] = o;
}

// ==================== launch (single stream — harness-safe) ====================
extern "C" void kernel_launch(void* const* d_in, const int* in_sizes, int n_in,
                              void* d_out, int out_size) {
    const float* x    = (const float*)d_in[0];
    const int*   ei   = (const int*)d_in[1];
    const float* Wgcn = (const float*)d_in[2];
    const float* bgcn = (const float*)d_in[3];
    const float* Wfc  = (const float*)d_in[4];
    const float* bfc  = (const float*)d_in[5];
    float* out = (float*)d_out;

    int n = in_sizes[0] / F;       // 100000
    int e = in_sizes[1] / 2;       // 1600000

    static bool attr_set = false;
    if (!attr_set) {
        cudaFuncSetAttribute(k_xw, cudaFuncAttributeMaxDynamicSharedMemorySize,
                             (F * C_OUT + 128 * F) * 4);
        attr_set = true;
    }

    int nbs = (n + 1023) / 1024;   // 98 (<=128)

    k_setup<<<1024 + 1 + nbs, 256>>>(Wgcn, Wfc, bgcn, bfc, n);

    int hthreads = (e + 3) / 4;
    k_hist<<<(hthreads + 255) / 256, 256>>>(ei + e, e);

    k_scan1<<<nbs, 256>>>(n);
    k_scan3<<<nbs, 256>>>(n, e, nbs);

    int fthreads = (e + 3) / 4;
    k_fill<<<(fthreads + 255) / 256, 256>>>(ei, e);

    int gemm_blocks = (n + 127) / 128;
    k_xw<<<gemm_blocks, 256, (F * C_OUT + 128 * F) * 4>>>(x, n);

    k_gather<<<(n * 16 + 255) / 256, 256>>>(out, n);
}